// round 5
// baseline (speedup 1.0000x reference)
#include <cuda_runtime.h>
#include <math_constants.h>

// ---------------------------------------------------------------------------
// MultiTaskLossWrapper fused single-kernel implementation.
// Inputs: 0 hazard3d f32[B], 1 hazard1d f32[B], 2 survtime f32[B],
//         3 censor f32[B], 4 vars_ f32[4], 5 beta1, 6 beta2,
//         7 age i32[B], 8 grade i32[B].  Output: f32[1]
//
// One launch, grid=128 blocks (<=148 SMs -> all co-resident, manual grid
// barrier is deadlock-free). No fp atomics; fully deterministic.
// ---------------------------------------------------------------------------

#define G 128
#define T 512
#define BMAX 4096
#define EPB 32              // elements per block = BMAX / G
#define HITILE 128
#define LOWTILE 512

__constant__ float c_risk_table[9] = {1.0f, 1.0f, 0.91f, 1.12f, 1.71f,
                                      2.41f, 3.27f, 5.18f, 8.44f};

__device__ float4 g_sp[BMAX];          // (surv, exp(h3), exp(h1), censor)
__device__ int    g_bcnt[4][G];        // per-block list counts
__device__ int    g_meta[4][BMAX];     // (orig_idx<<4) | decade_bucket
__device__ float  g_hl[4][BMAX];       // hazard3d
__device__ float2 g_coxp[G];           // per-block cox partials
__device__ float4 g_pairp[G];          // per-block pair partials

// sense-reversal grid barrier state (count returns to 0 each barrier;
// phase increases monotonically across replays -> replay-safe)
__device__ int               g_bar_count = 0;
__device__ volatile unsigned g_bar_phase = 0;

__device__ __forceinline__ void grid_barrier() {
    __syncthreads();
    if (threadIdx.x == 0) {
        unsigned ph = g_bar_phase;
        __threadfence();
        if (atomicAdd(&g_bar_count, 1) == G - 1) {
            g_bar_count = 0;
            __threadfence();
            g_bar_phase = ph + 1;
        } else {
            while (g_bar_phase == ph) { }
        }
        __threadfence();
    }
    __syncthreads();
}

__device__ __forceinline__ float warpSumF(float v) {
#pragma unroll
    for (int o = 16; o; o >>= 1) v += __shfl_xor_sync(0xffffffffu, v, o);
    return v;
}
__device__ __forceinline__ int warpSumI(int v) {
#pragma unroll
    for (int o = 16; o; o >>= 1) v += __shfl_xor_sync(0xffffffffu, v, o);
    return v;
}

__global__ void __launch_bounds__(T)
fused_kernel(const float* __restrict__ h3, const float* __restrict__ h1,
             const float* __restrict__ surv, const float* __restrict__ cen,
             const float* __restrict__ vars,
             const float* __restrict__ b1p, const float* __restrict__ b2p,
             const int* __restrict__ age, const int* __restrict__ grade,
             float* __restrict__ out, int B) {
    __shared__ int   s_base[4], s_tot[4];
    __shared__ float s_c3[16], s_c1[16];
    __shared__ float tabL[81], tabH[81];
    __shared__ int   smeta[HITILE];
    __shared__ float shh[HITILE];
    __shared__ float s_pr[4][16];

    const int b    = blockIdx.x;
    const int tid  = threadIdx.x;
    const int w    = tid >> 5;
    const int lane = tid & 31;

    // ---------------- phase A ---------------------------------------------
    int   meta = 0, mylist = -1, localpos = 0;
    float hval = 0.0f;
    if (w == 0) {
        int e = b * EPB + lane;
        bool valid = (e < B);
        if (valid) {
            float sv = surv[e], v3 = h3[e], v1 = h1[e], cv = cen[e];
            int a_ = age[e], g_ = grade[e];
            g_sp[e] = make_float4(sv, __expf(v3), __expf(v1), cv);
            int bkt = a_ / 10; if (bkt > 8) bkt = 8; if (bkt < 0) bkt = 0;
            meta = (e << 4) | bkt;
            hval = v3;
            if (g_ == 0)                    mylist = (a_ < 40) ? 0 : 1;
            else if (g_ == 1 || g_ == 2)    mylist = (a_ < 65) ? 2 : 3;
        }
#pragma unroll
        for (int l = 0; l < 4; l++) {
            unsigned mk = __ballot_sync(0xffffffffu, mylist == l);
            if (mylist == l) localpos = __popc(mk & ((1u << lane) - 1u));
            if (lane == 0) g_bcnt[l][b] = __popc(mk);
        }
    } else if (tid >= 128 && tid < 209) {
        // alpha tables (needed only after bar2)
        int i = tid - 128;
        float b1 = *b1p;
        int bi = i / 9, bj = i % 9;
        float d = (c_risk_table[bj] - c_risk_table[bi]) * 0.125f;
        tabL[i] = d / (1.0f + __expf(-b1 * d));
    } else if (tid >= 256 && tid < 337) {
        int i = tid - 256;
        float b2 = *b2p;
        int bi = i / 9, bj = i % 9;
        float d = (c_risk_table[bj] - c_risk_table[bi]) * 0.125f;
        tabH[i] = d / (1.0f + __expf(-b2 * d));
    }

    grid_barrier();   // g_sp + g_bcnt complete everywhere

    // ---------------- phase B: bases, scatter, cox -------------------------
    if (w < 4) {
        // warp l: prefix (<b) and total of g_bcnt[l][*]
        int acc_lt = 0, acc_tot = 0;
#pragma unroll
        for (int c = 0; c < G; c += 32) {
            int idx = c + lane;
            int v = g_bcnt[w][idx];
            acc_tot += v;
            acc_lt  += (idx < b) ? v : 0;
        }
        acc_lt  = warpSumI(acc_lt);
        acc_tot = warpSumI(acc_tot);
        if (lane == 0) { s_base[w] = acc_lt; s_tot[w] = acc_tot; }
    }
    __syncthreads();
    if (w == 0 && mylist >= 0) {
        int pos = s_base[mylist] + localpos;
        g_meta[mylist][pos] = meta;
        g_hl[mylist][pos]   = hval;
    }

    // cox: 2 rows per warp, full column sweep over L2-resident g_sp
    {
        int r0 = b * EPB + w * 2;
        int r1 = r0 + 1;
        float4 q0 = (r0 < B) ? g_sp[r0] : make_float4(CUDART_INF_F, 1.f, 1.f, 0.f);
        float4 q1 = (r1 < B) ? g_sp[r1] : make_float4(CUDART_INF_F, 1.f, 1.f, 0.f);
        float si0 = q0.x, si1 = q1.x;
        float s3a = 0.f, s1a = 0.f, s3b = 0.f, s1b = 0.f;
        const float4* __restrict__ sp = g_sp;
#pragma unroll 4
        for (int j = lane; j < B; j += 32) {
            float4 p = __ldg(&sp[j]);
            if (p.x >= si0) { s3a += p.y; s1a += p.z; }
            if (p.x >= si1) { s3b += p.y; s1b += p.z; }
        }
        s3a = warpSumF(s3a); s1a = warpSumF(s1a);
        s3b = warpSumF(s3b); s1b = warpSumF(s1b);
        if (lane == 0) {
            float c3 = 0.f, c1 = 0.f;
            if (r0 < B) {
                c3 += q0.w * __logf(__fdividef(q0.y, s3a));
                c1 += q0.w * __logf(__fdividef(q0.z, s1a));
            }
            if (r1 < B) {
                c3 += q1.w * __logf(__fdividef(q1.y, s3b));
                c1 += q1.w * __logf(__fdividef(q1.z, s1b));
            }
            s_c3[w] = c3; s_c1[w] = c1;
        }
    }
    __syncthreads();
    if (w == 0) {
        float c3 = (lane < 16) ? s_c3[lane] : 0.f;
        float c1 = (lane < 16) ? s_c1[lane] : 0.f;
        c3 = warpSumF(c3); c1 = warpSumF(c1);
        if (lane == 0) g_coxp[b] = make_float2(c3, c1);
    }

    grid_barrier();   // lists complete everywhere

    // ---------------- phase C: pair-rank tiles -----------------------------
    {
        const int nLL = s_tot[0], nHL = s_tot[1], nLH = s_tot[2], nHH = s_tot[3];
        const int tlL = (nLL + LOWTILE - 1) / LOWTILE;
        const int thL = (nHL + HITILE - 1) / HITILE;
        const int tlH = (nLH + LOWTILE - 1) / LOWTILE;
        const int thH = (nHH + HITILE - 1) / HITILE;
        const int TL = tlL * thL;
        const int NT = TL + tlH * thH;

        float accS0 = 0.f, accC0 = 0.f, accS1 = 0.f, accC1 = 0.f;

        for (int t = b; t < NT; t += G) {
            int prob, lt, ht, nLow, nHigh, llist, hlist;
            if (t < TL) { prob = 0; lt = t / thL; ht = t - lt * thL;
                          nLow = nLL; nHigh = nHL; llist = 0; hlist = 1; }
            else        { int tt = t - TL; prob = 1; lt = tt / thH; ht = tt - lt * thH;
                          nLow = nLH; nHigh = nHH; llist = 2; hlist = 3; }

            int j0 = ht * HITILE;
            int hcount = nHigh - j0;
            if (hcount > HITILE) hcount = HITILE;

            __syncthreads();
            if (tid < hcount) {
                smeta[tid] = g_meta[hlist][j0 + tid];
                shh[tid]   = g_hl[hlist][j0 + tid];
            }
            __syncthreads();

            int li = lt * LOWTILE + tid;
            if (li < nLow) {
                int mi = g_meta[llist][li];
                int idxi = mi >> 4;
                const float* tab = prob ? tabH : tabL;
                int rowoff = (mi & 15) * 9;
                float hi = g_hl[llist][li];
                float s = 0.f, c = 0.f;
                for (int jj = 0; jj < hcount; jj++) {
                    int mj = smeta[jj];
                    if ((mj >> 4) > idxi) {
                        float alpha = tab[rowoff + (mj & 15)];
                        float xv = alpha * (hi - shh[jj]);
                        float e = __expf(-fabsf(xv));
                        s += fmaxf(xv, 0.f) + __logf(1.0f + e);
                        c += 1.f;
                    }
                }
                if (prob == 0) { accS0 += s; accC0 += c; }
                else           { accS1 += s; accC1 += c; }
            }
        }

        accS0 = warpSumF(accS0); accC0 = warpSumF(accC0);
        accS1 = warpSumF(accS1); accC1 = warpSumF(accC1);
        if (lane == 0) {
            s_pr[0][w] = accS0; s_pr[1][w] = accC0;
            s_pr[2][w] = accS1; s_pr[3][w] = accC1;
        }
        __syncthreads();
        if (tid == 0) {
            float a = 0.f, bb = 0.f, c = 0.f, d = 0.f;
#pragma unroll
            for (int k = 0; k < 16; k++) {
                a += s_pr[0][k]; bb += s_pr[1][k];
                c += s_pr[2][k]; d  += s_pr[3][k];
            }
            g_pairp[b] = make_float4(a, bb, c, d);
        }
    }

    grid_barrier();   // all partials written

    // ---------------- phase D: block 0 final combine -----------------------
    if (b == 0) {
        float a0 = 0.f, a1 = 0.f, a2 = 0.f, a3 = 0.f, a4 = 0.f, a5 = 0.f;
        if (tid < G) {
            float2 cp = g_coxp[tid];
            float4 pp = g_pairp[tid];
            a0 = cp.x; a1 = cp.y;
            a2 = pp.x; a3 = pp.y; a4 = pp.z; a5 = pp.w;
        }
        a0 = warpSumF(a0); a1 = warpSumF(a1); a2 = warpSumF(a2);
        a3 = warpSumF(a3); a4 = warpSumF(a4); a5 = warpSumF(a5);
        __shared__ float fr[6][16];
        if (lane == 0 && w < 4) {
            fr[0][w] = a0; fr[1][w] = a1; fr[2][w] = a2;
            fr[3][w] = a3; fr[4][w] = a4; fr[5][w] = a5;
        }
        __syncthreads();
        if (tid == 0) {
            float s0 = 0.f, s1 = 0.f, s2 = 0.f, s3 = 0.f, s4 = 0.f, s5 = 0.f;
#pragma unroll
            for (int k = 0; k < 4; k++) {
                s0 += fr[0][k]; s1 += fr[1][k]; s2 += fr[2][k];
                s3 += fr[3][k]; s4 += fr[4][k]; s5 += fr[5][k];
            }
            float invB = 1.0f / (float)B;
            float loss3d = -s0 * invB;
            float loss1d = -s1 * invB;
            float lgg = (s3 > 0.5f) ? (s2 / s3) : 0.0f;
            float hgg = (s5 > 0.5f) ? (s4 / s5) : 0.0f;
            float losscli = lgg + hgg;
            float v0 = vars[0], v2 = vars[2], v3 = vars[3];
            out[0] = 0.5f * loss3d / (v0 * v0) + logf(v0)
                   + 0.5f * loss1d / (v2 * v2) + logf(v2)
                   + 0.5f * losscli / (v3 * v3) + logf(v3);
        }
    }
}

extern "C" void kernel_launch(void* const* d_in, const int* in_sizes, int n_in,
                              void* d_out, int out_size) {
    const float* h3     = (const float*)d_in[0];
    const float* h1     = (const float*)d_in[1];
    const float* surv   = (const float*)d_in[2];
    const float* censor = (const float*)d_in[3];
    const float* vars   = (const float*)d_in[4];
    const float* beta1  = (const float*)d_in[5];
    const float* beta2  = (const float*)d_in[6];
    const int*   age    = (const int*)d_in[7];
    const int*   grade  = (const int*)d_in[8];
    int B = in_sizes[0];

    fused_kernel<<<G, T>>>(h3, h1, surv, censor, vars, beta1, beta2,
                           age, grade, (float*)d_out, B);
}

// round 6
// speedup vs baseline: 1.1782x; 1.1782x over previous
#include <cuda_runtime.h>
#include <math_constants.h>

// ---------------------------------------------------------------------------
// MultiTaskLossWrapper fused single-kernel implementation (v2: smem-staged Cox)
// Inputs: 0 hazard3d f32[B], 1 hazard1d f32[B], 2 survtime f32[B],
//         3 censor f32[B], 4 vars_ f32[4], 5 beta1, 6 beta2,
//         7 age i32[B], 8 grade i32[B].  Output: f32[1]
//
// One launch, grid=128 blocks (all co-resident on 148 SMs -> manual grid
// barrier deadlock-free). No fp atomics; fully deterministic.
// ---------------------------------------------------------------------------

#define G 128
#define T 512
#define BMAX 4096
#define EPB 32               // rows per block = BMAX / G
#define NROW 8               // rows per warp (4 row-groups)
#define NCHK 4               // column chunks (4 * 1024 = BMAX)
#define CHKW 1024
#define HITILE 128
#define LOWTILE 512

__constant__ float c_risk_table[9] = {1.0f, 1.0f, 0.91f, 1.12f, 1.71f,
                                      2.41f, 3.27f, 5.18f, 8.44f};

__device__ float4 g_sp[BMAX];          // (surv, exp(h3), exp(h1), censor)
__device__ int    g_bcnt[4][G];        // per-block list counts
__device__ int    g_meta[4][BMAX];     // (orig_idx<<4) | decade_bucket
__device__ float  g_hl[4][BMAX];       // hazard3d
__device__ float2 g_coxp[G];           // per-block cox partials
__device__ float4 g_pairp[G];          // per-block pair partials

// sense-reversal grid barrier (phase monotone across replays -> replay-safe)
__device__ int               g_bar_count = 0;
__device__ volatile unsigned g_bar_phase = 0;

__device__ __forceinline__ void grid_barrier() {
    __syncthreads();
    if (threadIdx.x == 0) {
        unsigned ph = g_bar_phase;
        __threadfence();
        if (atomicAdd(&g_bar_count, 1) == G - 1) {
            g_bar_count = 0;
            __threadfence();
            g_bar_phase = ph + 1;
        } else {
            while (g_bar_phase == ph) { }
        }
        __threadfence();
    }
    __syncthreads();
}

__device__ __forceinline__ float warpSumF(float v) {
#pragma unroll
    for (int o = 16; o; o >>= 1) v += __shfl_xor_sync(0xffffffffu, v, o);
    return v;
}
__device__ __forceinline__ int warpSumI(int v) {
#pragma unroll
    for (int o = 16; o; o >>= 1) v += __shfl_xor_sync(0xffffffffu, v, o);
    return v;
}

__global__ void __launch_bounds__(T)
fused_kernel(const float* __restrict__ h3, const float* __restrict__ h1,
             const float* __restrict__ surv, const float* __restrict__ cen,
             const float* __restrict__ vars,
             const float* __restrict__ b1p, const float* __restrict__ b2p,
             const int* __restrict__ age, const int* __restrict__ grade,
             float* __restrict__ out, int B) {
    extern __shared__ float4 s_sp[];     // [BMAX] staged (surv,e3,e1,cen)

    __shared__ int   s_base[4], s_tot[4];
    __shared__ float s_part3[EPB][NCHK], s_part1[EPB][NCHK];
    __shared__ float tabL[81], tabH[81];
    __shared__ int   smeta[HITILE];
    __shared__ float shh[HITILE];
    __shared__ float s_pr[4][16];

    const int b    = blockIdx.x;
    const int tid  = threadIdx.x;
    const int w    = tid >> 5;
    const int lane = tid & 31;

    // ---------------- phase A: load 32 elems (warp 0), tables --------------
    int   meta = 0, mylist = -1, localpos = 0;
    float hval = 0.0f;
    if (w == 0) {
        int e = b * EPB + lane;
        bool valid = (e < B);
        if (valid) {
            float sv = surv[e], v3 = h3[e], v1 = h1[e], cv = cen[e];
            int a_ = age[e], g_ = grade[e];
            g_sp[e] = make_float4(sv, __expf(v3), __expf(v1), cv);
            int bkt = a_ / 10; if (bkt > 8) bkt = 8; if (bkt < 0) bkt = 0;
            meta = (e << 4) | bkt;
            hval = v3;
            if (g_ == 0)                 mylist = (a_ < 40) ? 0 : 1;
            else if (g_ == 1 || g_ == 2) mylist = (a_ < 65) ? 2 : 3;
        }
#pragma unroll
        for (int l = 0; l < 4; l++) {
            unsigned mk = __ballot_sync(0xffffffffu, mylist == l);
            if (mylist == l) localpos = __popc(mk & ((1u << lane) - 1u));
            if (lane == 0) g_bcnt[l][b] = __popc(mk);
        }
    } else if (tid >= 128 && tid < 209) {
        int i = tid - 128;
        float b1 = *b1p;
        int bi = i / 9, bj = i % 9;
        float d = (c_risk_table[bj] - c_risk_table[bi]) * 0.125f;
        tabL[i] = d / (1.0f + __expf(-b1 * d));
    } else if (tid >= 256 && tid < 337) {
        int i = tid - 256;
        float b2 = *b2p;
        int bi = i / 9, bj = i % 9;
        float d = (c_risk_table[bj] - c_risk_table[bi]) * 0.125f;
        tabH[i] = d / (1.0f + __expf(-b2 * d));
    }

    grid_barrier();   // g_sp + g_bcnt complete everywhere

    // ---------------- phase B: bases, stage smem, scatter, cox -------------
    if (w < 4) {
        int acc_lt = 0, acc_tot = 0;
#pragma unroll
        for (int c = 0; c < G; c += 32) {
            int idx = c + lane;
            int v = g_bcnt[w][idx];
            acc_tot += v;
            acc_lt  += (idx < b) ? v : 0;
        }
        acc_lt  = warpSumI(acc_lt);
        acc_tot = warpSumI(acc_tot);
        if (lane == 0) { s_base[w] = acc_lt; s_tot[w] = acc_tot; }
    }

    // stage full g_sp into shared (8 float4 per thread, coalesced)
#pragma unroll
    for (int k = 0; k < BMAX / T; k++) {
        int idx = k * T + tid;
        s_sp[idx] = (idx < B) ? __ldg(&g_sp[idx])
                              : make_float4(-CUDART_INF_F, 0.0f, 0.0f, 0.0f);
    }
    __syncthreads();

    if (w == 0 && mylist >= 0) {
        int pos = s_base[mylist] + localpos;
        g_meta[mylist][pos] = meta;
        g_hl[mylist][pos]   = hval;
    }

    // cox sweep: warp = (row-group rg, column-chunk cc)
    {
        const int rg = w & 3;          // 4 row groups of 8 rows
        const int cc = w >> 2;         // 4 column chunks of 1024
        const int rbase = b * EPB + rg * NROW;

        float si[NROW], s3[NROW], s1[NROW];
#pragma unroll
        for (int k = 0; k < NROW; k++) {
            int r = rbase + k;
            si[k] = (r < B) ? s_sp[r].x : CUDART_INF_F;
            s3[k] = 0.0f; s1[k] = 0.0f;
        }
        const int cbase = cc * CHKW + lane;
#pragma unroll 2
        for (int it = 0; it < CHKW / 32; it++) {
            float4 p = s_sp[cbase + it * 32];
#pragma unroll
            for (int k = 0; k < NROW; k++) {
                if (p.x >= si[k]) { s3[k] += p.y; s1[k] += p.z; }
            }
        }
#pragma unroll
        for (int k = 0; k < NROW; k++) {
            s3[k] = warpSumF(s3[k]);
            s1[k] = warpSumF(s1[k]);
            if (lane == 0) {
                s_part3[rg * NROW + k][cc] = s3[k];
                s_part1[rg * NROW + k][cc] = s1[k];
            }
        }
    }
    __syncthreads();

    if (w == 0) {
        // lane r handles row b*32+r: combine 4 chunks in fixed order
        int r = b * EPB + lane;
        float c3 = 0.0f, c1 = 0.0f;
        if (r < B) {
            float t3 = s_part3[lane][0] + s_part3[lane][1]
                     + s_part3[lane][2] + s_part3[lane][3];
            float t1 = s_part1[lane][0] + s_part1[lane][1]
                     + s_part1[lane][2] + s_part1[lane][3];
            float4 q = s_sp[r];
            c3 = q.w * __logf(__fdividef(q.y, t3));
            c1 = q.w * __logf(__fdividef(q.z, t1));
        }
        c3 = warpSumF(c3);
        c1 = warpSumF(c1);
        if (lane == 0) g_coxp[b] = make_float2(c3, c1);
    }

    grid_barrier();   // lists + cox partials complete everywhere

    // ---------------- phase C: pair-rank tiles -----------------------------
    {
        const int nLL = s_tot[0], nHL = s_tot[1], nLH = s_tot[2], nHH = s_tot[3];
        const int tlL = (nLL + LOWTILE - 1) / LOWTILE;
        const int thL = (nHL + HITILE - 1) / HITILE;
        const int tlH = (nLH + LOWTILE - 1) / LOWTILE;
        const int thH = (nHH + HITILE - 1) / HITILE;
        const int TL = tlL * thL;
        const int NT = TL + tlH * thH;

        float accS0 = 0.f, accC0 = 0.f, accS1 = 0.f, accC1 = 0.f;

        for (int t = b; t < NT; t += G) {
            int prob, lt, ht, nLow, nHigh, llist, hlist;
            if (t < TL) { prob = 0; lt = t / thL; ht = t - lt * thL;
                          nLow = nLL; nHigh = nHL; llist = 0; hlist = 1; }
            else        { int tt = t - TL; prob = 1; lt = tt / thH; ht = tt - lt * thH;
                          nLow = nLH; nHigh = nHH; llist = 2; hlist = 3; }

            int j0 = ht * HITILE;
            int hcount = nHigh - j0;
            if (hcount > HITILE) hcount = HITILE;

            __syncthreads();
            if (tid < hcount) {
                smeta[tid] = g_meta[hlist][j0 + tid];
                shh[tid]   = g_hl[hlist][j0 + tid];
            }
            __syncthreads();

            int li = lt * LOWTILE + tid;
            if (li < nLow) {
                int mi = g_meta[llist][li];
                int idxi = mi >> 4;
                const float* tab = prob ? tabH : tabL;
                int rowoff = (mi & 15) * 9;
                float hi = g_hl[llist][li];
                float s = 0.f, c = 0.f;
                for (int jj = 0; jj < hcount; jj++) {
                    int mj = smeta[jj];
                    if ((mj >> 4) > idxi) {
                        float alpha = tab[rowoff + (mj & 15)];
                        float xv = alpha * (hi - shh[jj]);
                        float e = __expf(-fabsf(xv));
                        s += fmaxf(xv, 0.f) + __logf(1.0f + e);
                        c += 1.f;
                    }
                }
                if (prob == 0) { accS0 += s; accC0 += c; }
                else           { accS1 += s; accC1 += c; }
            }
        }

        accS0 = warpSumF(accS0); accC0 = warpSumF(accC0);
        accS1 = warpSumF(accS1); accC1 = warpSumF(accC1);
        if (lane == 0) {
            s_pr[0][w] = accS0; s_pr[1][w] = accC0;
            s_pr[2][w] = accS1; s_pr[3][w] = accC1;
        }
        __syncthreads();
        if (tid == 0) {
            float a = 0.f, bb = 0.f, c = 0.f, d = 0.f;
#pragma unroll
            for (int k = 0; k < 16; k++) {
                a += s_pr[0][k]; bb += s_pr[1][k];
                c += s_pr[2][k]; d  += s_pr[3][k];
            }
            g_pairp[b] = make_float4(a, bb, c, d);
        }
    }

    grid_barrier();   // all partials written

    // ---------------- phase D: block 0 final combine -----------------------
    if (b == 0) {
        float a0 = 0.f, a1 = 0.f, a2 = 0.f, a3 = 0.f, a4 = 0.f, a5 = 0.f;
        if (tid < G) {
            float2 cp = g_coxp[tid];
            float4 pp = g_pairp[tid];
            a0 = cp.x; a1 = cp.y;
            a2 = pp.x; a3 = pp.y; a4 = pp.z; a5 = pp.w;
        }
        a0 = warpSumF(a0); a1 = warpSumF(a1); a2 = warpSumF(a2);
        a3 = warpSumF(a3); a4 = warpSumF(a4); a5 = warpSumF(a5);
        __shared__ float fr[6][16];
        if (lane == 0 && w < 4) {
            fr[0][w] = a0; fr[1][w] = a1; fr[2][w] = a2;
            fr[3][w] = a3; fr[4][w] = a4; fr[5][w] = a5;
        }
        __syncthreads();
        if (tid == 0) {
            float s0 = 0.f, s1 = 0.f, s2 = 0.f, s3 = 0.f, s4 = 0.f, s5 = 0.f;
#pragma unroll
            for (int k = 0; k < 4; k++) {
                s0 += fr[0][k]; s1 += fr[1][k]; s2 += fr[2][k];
                s3 += fr[3][k]; s4 += fr[4][k]; s5 += fr[5][k];
            }
            float invB = 1.0f / (float)B;
            float loss3d = -s0 * invB;
            float loss1d = -s1 * invB;
            float lgg = (s3 > 0.5f) ? (s2 / s3) : 0.0f;
            float hgg = (s5 > 0.5f) ? (s4 / s5) : 0.0f;
            float losscli = lgg + hgg;
            float v0 = vars[0], v2 = vars[2], v3 = vars[3];
            out[0] = 0.5f * loss3d / (v0 * v0) + logf(v0)
                   + 0.5f * loss1d / (v2 * v2) + logf(v2)
                   + 0.5f * losscli / (v3 * v3) + logf(v3);
        }
    }
}

extern "C" void kernel_launch(void* const* d_in, const int* in_sizes, int n_in,
                              void* d_out, int out_size) {
    const float* h3     = (const float*)d_in[0];
    const float* h1     = (const float*)d_in[1];
    const float* surv   = (const float*)d_in[2];
    const float* censor = (const float*)d_in[3];
    const float* vars   = (const float*)d_in[4];
    const float* beta1  = (const float*)d_in[5];
    const float* beta2  = (const float*)d_in[6];
    const int*   age    = (const int*)d_in[7];
    const int*   grade  = (const int*)d_in[8];
    int B = in_sizes[0];

    size_t smem = (size_t)BMAX * sizeof(float4);   // 64KB
    cudaFuncSetAttribute(fused_kernel, cudaFuncAttributeMaxDynamicSharedMemorySize,
                         (int)smem);
    fused_kernel<<<G, T, smem>>>(h3, h1, surv, censor, vars, beta1, beta2,
                                 age, grade, (float*)d_out, B);
}

// round 7
// speedup vs baseline: 1.6631x; 1.4116x over previous
#include <cuda_runtime.h>
#include <math_constants.h>

// ---------------------------------------------------------------------------
// MultiTaskLossWrapper — fully barrier-free single-kernel implementation.
// Each block is self-sufficient: stages all inputs itself, builds the pair
// lists itself (identical & deterministic in every block), computes cox for
// its 32 rows and its share of pair units, writes partials; the LAST block
// (atomic ticket) combines partials in fixed order -> deterministic scalar.
// Inputs: 0 hazard3d f32[B], 1 hazard1d f32[B], 2 survtime f32[B],
//         3 censor f32[B], 4 vars_ f32[4], 5 beta1, 6 beta2,
//         7 age i32[B], 8 grade i32[B].  Output: f32[1]
// ---------------------------------------------------------------------------

#define G 128
#define T 512
#define NW 16
#define TOTW (G * NW)
#define BMAX 4096
#define EPB 32
#define NK 8                   // 8 groups of 32 per warp = 256 elems/warp
#define LISTPAD (BMAX + 128)   // lists padded to multiples of 32

__constant__ float c_risk_table[9] = {1.0f, 1.0f, 0.91f, 1.12f, 1.71f,
                                      2.41f, 3.27f, 5.18f, 8.44f};

__device__ float2 g_coxp[G];
__device__ float4 g_pairp[G];
__device__ int    g_ticket = 0;   // finisher resets to 0 -> replay-safe

__device__ __forceinline__ float warpSumF(float v) {
#pragma unroll
    for (int o = 16; o; o >>= 1) v += __shfl_xor_sync(0xffffffffu, v, o);
    return v;
}

__global__ void __launch_bounds__(T)
fused_kernel(const float* __restrict__ h3, const float* __restrict__ h1,
             const float* __restrict__ surv, const float* __restrict__ cen,
             const float* __restrict__ vars,
             const float* __restrict__ b1p, const float* __restrict__ b2p,
             const int* __restrict__ age, const int* __restrict__ grade,
             float* __restrict__ out, int B) {
    extern __shared__ float sm[];
    float* s_surv  = sm;                            // [BMAX]
    float* s_e3    = sm + BMAX;                     // [BMAX]
    float* s_e1    = sm + 2 * BMAX;                 // [BMAX]
    float* s_h3    = sm + 3 * BMAX;                 // [BMAX]
    int*   s_lmeta = (int*)(sm + 4 * BMAX);         // [LISTPAD]
    float* s_lh    = sm + 4 * BMAX + LISTPAD;       // [LISTPAD]

    __shared__ int   s_gc[4][G];          // per-(list, 32-elem group) counts->bases
    __shared__ int   s_tot[4], s_off[5];
    __shared__ float tabL[81], tabH[81];
    __shared__ float s_p3[EPB][4], s_p1[EPB][4];
    __shared__ float s_pr[4][NW];
    __shared__ float s_fin[6][4];
    __shared__ int   s_last;

    const int b = blockIdx.x, tid = threadIdx.x;
    const int w = tid >> 5, lane = tid & 31;

    // ---- alpha tables (81 bucket-pairs per problem) -----------------------
    if (tid < 162) {
        bool isL = tid < 81;
        int i = isL ? tid : tid - 81;
        float bb = isL ? *b1p : *b2p;
        float d = (c_risk_table[i % 9] - c_risk_table[i / 9]) * 0.125f;
        float al = __fdividef(d, 1.0f + __expf(-bb * d));
        if (isL) tabL[i] = al; else tabH[i] = al;
    }

    // ---- stage inputs + per-group list counts (warp w owns 256 elems) -----
    unsigned mlpack = 0u, bkpack = 0u;
#pragma unroll
    for (int k = 0; k < NK; k++) {
        int e = w * (NK * 32) + k * 32 + lane;
        bool valid = (e < B);
        int a_ = -1, g_ = -1;
        if (valid) {
            float sv = surv[e], v3 = h3[e], v1 = h1[e];
            a_ = age[e]; g_ = grade[e];
            s_surv[e] = sv;
            s_e3[e] = __expf(v3);
            s_e1[e] = __expf(v1);
            s_h3[e] = v3;
        }
        int ml = -1;
        if (g_ == 0)                 ml = (a_ < 40) ? 0 : 1;
        else if (g_ == 1 || g_ == 2) ml = (a_ < 65) ? 2 : 3;
        int bkt = a_ / 10; bkt = bkt < 0 ? 0 : (bkt > 8 ? 8 : bkt);
        mlpack |= (unsigned)(ml + 1) << (3 * k);
        bkpack |= (unsigned)bkt << (4 * k);
#pragma unroll
        for (int l = 0; l < 4; l++) {
            unsigned mk = __ballot_sync(0xffffffffu, ml == l);
            if (lane == 0) s_gc[l][w * NK + k] = __popc(mk);
        }
    }
    for (int j = B + tid; j < BMAX; j += T) {
        s_surv[j] = -CUDART_INF_F; s_e3[j] = 0.0f; s_e1[j] = 0.0f;
    }
    __syncthreads();

    // ---- scan group counts -> exclusive bases (warp l scans list l) -------
    if (w < 4) {
        int l = w;
        int g0 = lane * 4;
        int v0 = s_gc[l][g0], v1 = s_gc[l][g0 + 1];
        int v2 = s_gc[l][g0 + 2], v3 = s_gc[l][g0 + 3];
        int ls = v0 + v1 + v2 + v3;
        int x = ls;
#pragma unroll
        for (int o = 1; o < 32; o <<= 1) {
            int y = __shfl_up_sync(0xffffffffu, x, o);
            if (lane >= o) x += y;
        }
        int base = x - ls;
        s_gc[l][g0]     = base;
        s_gc[l][g0 + 1] = base + v0;
        s_gc[l][g0 + 2] = base + v0 + v1;
        s_gc[l][g0 + 3] = base + v0 + v1 + v2;
        if (lane == 31) s_tot[l] = x;
    }
    __syncthreads();
    if (tid == 0) {
        int o = 0;
#pragma unroll
        for (int l = 0; l < 4; l++) { s_off[l] = o; o += (s_tot[l] + 31) & ~31; }
        s_off[4] = o;
    }
    __syncthreads();

    // ---- scatter list entries (element order preserved -> idx-sorted) ----
#pragma unroll
    for (int k = 0; k < NK; k++) {
        int ml = (int)((mlpack >> (3 * k)) & 7u) - 1;
        unsigned mymask = 0u;
#pragma unroll
        for (int l = 0; l < 4; l++) {
            unsigned mk = __ballot_sync(0xffffffffu, ml == l);
            if (ml == l) mymask = mk;
        }
        if (ml >= 0) {
            int e = w * (NK * 32) + k * 32 + lane;
            int bkt = (int)((bkpack >> (4 * k)) & 15u);
            int pos = s_off[ml] + s_gc[ml][w * NK + k]
                    + __popc(mymask & ((1u << lane) - 1u));
            s_lmeta[pos] = (e << 4) | bkt;
            s_lh[pos] = s_h3[e];
        }
    }
    // sentinel pads: low lists (0,2) -> huge idx (never a valid low row);
    // high lists (1,3) -> idx=-1 (never passes idxj > idxi)
#pragma unroll
    for (int l = 0; l < 4; l++) {
        int sent = (l == 0 || l == 2) ? 0x7FFFFFF0 : -16;
        for (int i = s_off[l] + s_tot[l] + tid; i < s_off[l + 1]; i += T) {
            s_lmeta[i] = sent; s_lh[i] = 0.0f;
        }
    }

    // ---- cox sweep: warp = (row-group rg of 8 rows, column-chunk cc) ------
    {
        const int rg = w & 3, cc = w >> 2;
        const int rbase = b * EPB + rg * 8;
        float si[8], a3[8], a1[8];
#pragma unroll
        for (int k = 0; k < 8; k++) {
            int r = rbase + k;
            si[k] = (r < B) ? s_surv[r] : CUDART_INF_F;
            a3[k] = 0.0f; a1[k] = 0.0f;
        }
        const int cb = cc * 1024 + lane;
#pragma unroll 4
        for (int it = 0; it < 32; it++) {
            int j = cb + it * 32;
            float pv = s_surv[j], pe3 = s_e3[j], pe1 = s_e1[j];
#pragma unroll
            for (int k = 0; k < 8; k++) {
                if (pv >= si[k]) { a3[k] += pe3; a1[k] += pe1; }
            }
        }
#pragma unroll
        for (int k = 0; k < 8; k++) {
            a3[k] = warpSumF(a3[k]);
            a1[k] = warpSumF(a1[k]);
            if (lane == 0) {
                s_p3[rg * 8 + k][cc] = a3[k];
                s_p1[rg * 8 + k][cc] = a1[k];
            }
        }
    }
    __syncthreads();   // cox partials + list scatter/pads all visible

    if (w == 0) {
        int r = b * EPB + lane;
        float c3 = 0.0f, c1 = 0.0f;
        if (r < B) {
            float t3 = s_p3[lane][0] + s_p3[lane][1] + s_p3[lane][2] + s_p3[lane][3];
            float t1 = s_p1[lane][0] + s_p1[lane][1] + s_p1[lane][2] + s_p1[lane][3];
            float cv = cen[r];
            c3 = cv * __logf(__fdividef(s_e3[r], t3));
            c1 = cv * __logf(__fdividef(s_e1[r], t1));
        }
        c3 = warpSumF(c3);
        c1 = warpSumF(c1);
        if (lane == 0) g_coxp[b] = make_float2(c3, c1);
    }

    // ---- pair phase: 32x32 warp units, grid-strided over all 2048 warps ---
    {
        const int n0 = s_tot[0], n1 = s_tot[1], n2 = s_tot[2], n3 = s_tot[3];
        const int uL = (n0 + 31) >> 5, vL = (n1 + 31) >> 5;
        const int uH = (n2 + 31) >> 5, vH = (n3 + 31) >> 5;
        const int NTL = uL * vL, NT = NTL + uH * vH;
        float aS0 = 0.f, aC0 = 0.f, aS1 = 0.f, aC1 = 0.f;
        const int gw = b * NW + w;

        for (int t = gw; t < NT; t += TOTW) {
            int prob, lu, hv, lo, ho, nHigh;
            const float* tab;
            if (t < NTL) {
                prob = 0; lu = t / vL; hv = t - lu * vL;
                lo = s_off[0]; ho = s_off[1]; nHigh = n1; tab = tabL;
            } else {
                int tt = t - NTL;
                prob = 1; lu = tt / vH; hv = tt - lu * vH;
                lo = s_off[2]; ho = s_off[3]; nHigh = n3; tab = tabH;
            }
            // early skip: lists are original-index sorted
            int lowMin = s_lmeta[lo + lu * 32] >> 4;
            int hlast = hv * 32 + 31; if (hlast > nHigh - 1) hlast = nHigh - 1;
            int highMax = s_lmeta[ho + hlast] >> 4;
            if (highMax < lowMin) continue;

            int li = lo + lu * 32 + lane;
            int mi = s_lmeta[li];
            int idxi = mi >> 4;
            int rowoff = (mi & 15) * 9;
            float hi = s_lh[li];
            int hbase = ho + hv * 32;
            float s = 0.0f, c = 0.0f;
#pragma unroll 4
            for (int r = 0; r < 32; r++) {
                int idx = hbase + ((lane + r) & 31);
                int mj = s_lmeta[idx];
                float hj = s_lh[idx];
                if ((mj >> 4) > idxi) {
                    float alpha = tab[rowoff + (mj & 15)];
                    float xv = alpha * (hi - hj);
                    s += fmaxf(xv, 0.0f) + __logf(1.0f + __expf(-fabsf(xv)));
                    c += 1.0f;
                }
            }
            if (prob == 0) { aS0 += s; aC0 += c; }
            else           { aS1 += s; aC1 += c; }
        }

        aS0 = warpSumF(aS0); aC0 = warpSumF(aC0);
        aS1 = warpSumF(aS1); aC1 = warpSumF(aC1);
        if (lane == 0) {
            s_pr[0][w] = aS0; s_pr[1][w] = aC0;
            s_pr[2][w] = aS1; s_pr[3][w] = aC1;
        }
    }
    __syncthreads();
    if (tid == 0) {
        float a = 0.f, bb = 0.f, c = 0.f, d = 0.f;
#pragma unroll
        for (int k = 0; k < NW; k++) {
            a += s_pr[0][k]; bb += s_pr[1][k];
            c += s_pr[2][k]; d  += s_pr[3][k];
        }
        g_pairp[b] = make_float4(a, bb, c, d);
    }

    // ---- ticket: last block combines (deterministic fixed-order sums) -----
    if (tid == 0) {
        __threadfence();
        int old = atomicAdd(&g_ticket, 1);
        s_last = (old == G - 1) ? 1 : 0;
    }
    __syncthreads();
    if (s_last) {
        if (tid == 0) { g_ticket = 0; __threadfence(); }
        float a0 = 0.f, a1 = 0.f, a2 = 0.f, a3 = 0.f, a4 = 0.f, a5 = 0.f;
        if (tid < G) {
            float2 cp = __ldcg(&g_coxp[tid]);
            float4 pp = __ldcg(&g_pairp[tid]);
            a0 = cp.x; a1 = cp.y;
            a2 = pp.x; a3 = pp.y; a4 = pp.z; a5 = pp.w;
        }
        a0 = warpSumF(a0); a1 = warpSumF(a1); a2 = warpSumF(a2);
        a3 = warpSumF(a3); a4 = warpSumF(a4); a5 = warpSumF(a5);
        if (lane == 0 && w < 4) {
            s_fin[0][w] = a0; s_fin[1][w] = a1; s_fin[2][w] = a2;
            s_fin[3][w] = a3; s_fin[4][w] = a4; s_fin[5][w] = a5;
        }
        __syncthreads();
        if (tid == 0) {
            float s0 = 0.f, s1 = 0.f, s2 = 0.f, s3 = 0.f, s4 = 0.f, s5 = 0.f;
#pragma unroll
            for (int k = 0; k < 4; k++) {
                s0 += s_fin[0][k]; s1 += s_fin[1][k]; s2 += s_fin[2][k];
                s3 += s_fin[3][k]; s4 += s_fin[4][k]; s5 += s_fin[5][k];
            }
            float invB = 1.0f / (float)B;
            float loss3d = -s0 * invB;
            float loss1d = -s1 * invB;
            float lgg = (s3 > 0.5f) ? (s2 / s3) : 0.0f;
            float hgg = (s5 > 0.5f) ? (s4 / s5) : 0.0f;
            float losscli = lgg + hgg;
            float v0 = vars[0], v2 = vars[2], v3 = vars[3];
            out[0] = 0.5f * loss3d / (v0 * v0) + logf(v0)
                   + 0.5f * loss1d / (v2 * v2) + logf(v2)
                   + 0.5f * losscli / (v3 * v3) + logf(v3);
        }
    }
}

extern "C" void kernel_launch(void* const* d_in, const int* in_sizes, int n_in,
                              void* d_out, int out_size) {
    const float* h3     = (const float*)d_in[0];
    const float* h1     = (const float*)d_in[1];
    const float* surv   = (const float*)d_in[2];
    const float* censor = (const float*)d_in[3];
    const float* vars   = (const float*)d_in[4];
    const float* beta1  = (const float*)d_in[5];
    const float* beta2  = (const float*)d_in[6];
    const int*   age    = (const int*)d_in[7];
    const int*   grade  = (const int*)d_in[8];
    int B = in_sizes[0];

    size_t smem = (size_t)(4 * BMAX + 2 * LISTPAD) * sizeof(float);  // ~97KB
    cudaFuncSetAttribute(fused_kernel, cudaFuncAttributeMaxDynamicSharedMemorySize,
                         (int)smem);
    fused_kernel<<<G, T, smem>>>(h3, h1, surv, censor, vars, beta1, beta2,
                                 age, grade, (float*)d_out, B);
}